// round 14
// baseline (speedup 1.0000x reference)
#include <cuda_runtime.h>
#include <cuda_fp16.h>
#include <cstdint>

#define D 128
#define K 64
#define TILE 128
#define NT_MAX 1563
#define NB 148
#define TEMP 30.0f
#define EPSn 1e-6f
#define ITERS 11

// smem byte offsets
#define OFF_MU 0                 // MuH 16KB | MuL 16KB (fp16)
#define OFF_X  32768             // buf0: Xh 32K | Xl 32K ; buf1 at +65536
#define OFF_CNT 163840           // sSum[512] | invS[128] | scnt[128]
#define SMEM_TOTAL (OFF_CNT + 4096)

__device__ __align__(16) unsigned char g_x[(size_t)NT_MAX * 65536]; // per tile: Xh 32K | Xl 32K, swizzled fp16
__device__ float g_mu_raw[(ITERS + 1) * K * D];
__device__ float g_cc[(ITERS + 1) * K];

__device__ __forceinline__ uint32_t smem_u32(const void* p) {
    uint32_t a;
    asm("{ .reg .u64 t; cvta.to.shared.u64 t, %1; cvt.u32.u64 %0, t; }" : "=r"(a) : "l"(p));
    return a;
}
__device__ __forceinline__ void ldsm_x4(uint32_t* r, uint32_t a) {
    asm volatile("ldmatrix.sync.aligned.m8n8.x4.shared.b16 {%0,%1,%2,%3}, [%4];"
        : "=r"(r[0]), "=r"(r[1]), "=r"(r[2]), "=r"(r[3]) : "r"(a));
}
__device__ __forceinline__ void ldsm_x4t(uint32_t* r, uint32_t a) {
    asm volatile("ldmatrix.sync.aligned.m8n8.x4.trans.shared.b16 {%0,%1,%2,%3}, [%4];"
        : "=r"(r[0]), "=r"(r[1]), "=r"(r[2]), "=r"(r[3]) : "r"(a));
}
__device__ __forceinline__ void mma_f16(float* c, const uint32_t* a, const uint32_t* b) {
    asm volatile("mma.sync.aligned.m16n8k16.row.col.f32.f16.f16.f32 "
        "{%0,%1,%2,%3}, {%4,%5,%6,%7}, {%8,%9}, {%0,%1,%2,%3};"
        : "+f"(c[0]), "+f"(c[1]), "+f"(c[2]), "+f"(c[3])
        : "r"(a[0]), "r"(a[1]), "r"(a[2]), "r"(a[3]), "r"(b[0]), "r"(b[1]));
}
__device__ __forceinline__ void cp16(uint32_t dst, const void* src) {
    asm volatile("cp.async.cg.shared.global [%0], [%1], 16;" :: "r"(dst), "l"(src) : "memory");
}
#define CP_COMMIT() asm volatile("cp.async.commit_group;" ::: "memory")
#define CP_WAIT0()  asm volatile("cp.async.wait_group 0;" ::: "memory")

__device__ __forceinline__ uint32_t pack_h2(__half a, __half b) {
    __half2 v(a, b);
    return *(uint32_t*)&v;
}
__device__ __forceinline__ uint32_t pack_f2h2(float a, float b) {
    __half2 v(__float2half(a), __float2half(b));
    return *(uint32_t*)&v;
}

// ---------------------------------------------------------------------------
// prep: normalize rows, split fp32 -> fp16 hi/lo, write swizzled tiles
__global__ void prep_kernel(const float* __restrict__ x, int N, int rowsPad) {
    int w = (blockIdx.x * blockDim.x + threadIdx.x) >> 5;
    int lane = threadIdx.x & 31;
    if (w >= rowsPad) return;
    float4 v = make_float4(0.f, 0.f, 0.f, 0.f);
    if (w < N) {
        v = ((const float4*)(x + (size_t)w * D))[lane];
        float ss = v.x*v.x + v.y*v.y + v.z*v.z + v.w*v.w;
        #pragma unroll
        for (int o = 16; o > 0; o >>= 1) ss += __shfl_xor_sync(0xffffffffu, ss, o);
        float inv = 1.0f / (sqrtf(ss) + EPSn);
        v.x *= inv; v.y *= inv; v.z *= inv; v.w *= inv;
    }
    float f[4] = {v.x, v.y, v.z, v.w};
    __half h[4], lo[4];
    #pragma unroll
    for (int i = 0; i < 4; i++) {
        h[i]  = __float2half(f[i]);
        lo[i] = __float2half(f[i] - __half2float(h[i]));
    }
    uint2 uh, ul;
    uh.x = pack_h2(h[0], h[1]);  uh.y = pack_h2(h[2], h[3]);
    ul.x = pack_h2(lo[0], lo[1]); ul.y = pack_h2(lo[2], lo[3]);
    int t = w >> 7, rl = w & 127, d0 = lane * 4;
    uint32_t off = (uint32_t)rl * 256 + ((((d0 >> 3) ^ (rl & 7)) & 15) << 4) + ((d0 & 7) << 1);
    unsigned char* base = g_x + (size_t)t * 65536;
    *(uint2*)(base + off)         = uh;
    *(uint2*)(base + 32768 + off) = ul;
}

// ---------------------------------------------------------------------------
__global__ void zero_kernel() {
    int i = blockIdx.x * 512 + threadIdx.x;
    if (i < ITERS * K * D) g_mu_raw[K * D + i] = 0.0f;
    if (i < (ITERS + 1) * K) g_cc[i] = 0.0f;
}

__global__ void final_mu_kernel(float* __restrict__ mu_out) {
    int k = blockIdx.x, d = threadIdx.x;
    mu_out[k * D + d] = g_mu_raw[ITERS * K * D + k * D + d] / g_cc[ITERS * K + k];
}

// ---------------------------------------------------------------------------
template<bool LAST>
__global__ void __launch_bounds__(256, 1) iter_kernel(float* __restrict__ r_out,
                                                      const float* __restrict__ mu_init,
                                                      int N, int nT, int it) {
    extern __shared__ unsigned char sm[];
    int tid = threadIdx.x, w = tid >> 5, lane = tid & 31;
    int bid = blockIdx.x;
    int t0 = (int)((long long)bid * nT / gridDim.x);
    int t1 = (int)((long long)(bid + 1) * nT / gridDim.x);
    if (t0 >= t1) return;
    uint32_t sb = smem_u32(sm);
    uint32_t sMuH = sb + OFF_MU;

    int g = lane >> 2, j = lane & 3;
    int kc0 = (w & 3) * 16;                 // kc strip (both GEMMs: m16)
    int R0  = (w >> 2) * 64;                // row half

    float* sSum = (float*)(sm + OFF_CNT);            // [4][128]
    float* invS = (float*)(sm + OFF_CNT + 2048);     // [128]
    float* scnt = (float*)(sm + OFF_CNT + 2560);     // [8][16]

    // issue X(t0) load (64KB) first
    {
        const unsigned char* gx = g_x + (size_t)t0 * 65536;
        #pragma unroll
        for (int jj = 0; jj < 16; jj++)
            cp16(sb + OFF_X + (tid + 256 * jj) * 16, gx + (tid + 256 * jj) * 16);
    }
    CP_COMMIT();

    // ---- fused mu update: v = raw/cnt, normalize, split fp16 hi/lo -> sMu ----
    {
        int kk = tid & 63, dpart = tid >> 6;
        const float* msrc = (it == 0) ? mu_init : (g_mu_raw + (size_t)it * (K * D));
        float cinv = (it == 0) ? 1.0f : (1.0f / g_cc[it * K + kk]);
        const float* row = msrc + kk * D + dpart * 32;
        float v[32];
        float ss = 0.0f;
        #pragma unroll
        for (int jj = 0; jj < 32; jj++) {
            float x = row[jj] * cinv;
            v[jj] = x;
            ss += x * x;
        }
        sSum[tid] = ss;
        __syncthreads();
        float tot = sSum[kk] + sSum[kk + 64] + sSum[kk + 128] + sSum[kk + 192];
        float inv = 1.0f / (sqrtf(tot) + EPSn);
        #pragma unroll
        for (int jj = 0; jj < 32; jj += 2) {
            float n0 = v[jj] * inv, n1 = v[jj + 1] * inv;
            __half h0 = __float2half(n0), h1 = __float2half(n1);
            __half l0 = __float2half(n0 - __half2float(h0));
            __half l1 = __float2half(n1 - __half2float(h1));
            int d = dpart * 32 + jj;
            uint32_t off = (uint32_t)kk * 256 + ((((d >> 3) ^ (kk & 7)) & 15) << 4) + ((d & 7) << 1);
            *(uint32_t*)(sm + OFF_MU + off)         = pack_h2(h0, h1);
            *(uint32_t*)(sm + OFF_MU + 16384 + off) = pack_h2(l0, l1);
        }
    }
    __syncthreads();

    // ---- hoist mu A-fragments (tile-invariant): 64 regs ----
    uint32_t aH[8][4], aL[8][4];
    #pragma unroll
    for (int ks = 0; ks < 8; ks++) {
        int ar = kc0 + (lane & 15);
        int ac = ks * 16 + ((lane >> 4) << 3);
        uint32_t addr = sMuH + (uint32_t)ar * 256 + ((((ac >> 3) ^ (ar & 7)) & 15) << 4);
        ldsm_x4(aH[ks], addr);
        ldsm_x4(aL[ks], addr + 16384);
    }
    CP_WAIT0();
    __syncthreads();

    float C2[16][4];
    #pragma unroll
    for (int f = 0; f < 16; f++)
        #pragma unroll
        for (int q = 0; q < 4; q++) C2[f][q] = 0.0f;
    float cacc0 = 0.0f, cacc1 = 0.0f;

    for (int t = t0; t < t1; t++) {
        int buf = (t - t0) & 1;
        uint32_t sX = sb + OFF_X + buf * 65536;       // Xh; Xl at +32768
        if (t + 1 < t1) {
            const unsigned char* gx = g_x + (size_t)(t + 1) * 65536;
            uint32_t dst = sb + OFF_X + (buf ^ 1) * 65536;
            #pragma unroll
            for (int jj = 0; jj < 16; jj++)
                cp16(dst + (tid + 256 * jj) * 16, gx + (tid + 256 * jj) * 16);
        }
        CP_COMMIT();

        // ---- GEMM1: C1[16 kc x 64 rows] = Mu . X^T (3-term, term-major ILP) ----
        float C1[8][4];
        #pragma unroll
        for (int f = 0; f < 8; f++)
            #pragma unroll
            for (int q = 0; q < 4; q++) C1[f][q] = 0.0f;
        #pragma unroll
        for (int ks = 0; ks < 8; ks++) {
            int xc = ks * 16 + (((lane >> 3) & 1) << 3);
            uint32_t bh[4][4], bl[4][4];
            #pragma unroll
            for (int pb = 0; pb < 4; pb++) {
                int xr = R0 + pb * 16 + ((lane >> 4) << 3) + (lane & 7);
                uint32_t addr = sX + (uint32_t)xr * 256 + ((((xc >> 3) ^ (xr & 7)) & 15) << 4);
                ldsm_x4(bh[pb], addr);
            }
            #pragma unroll
            for (int pb = 0; pb < 4; pb++) {
                mma_f16(C1[2*pb],   aH[ks], bh[pb]);
                mma_f16(C1[2*pb+1], aH[ks], bh[pb] + 2);
            }
            #pragma unroll
            for (int pb = 0; pb < 4; pb++) {
                int xr = R0 + pb * 16 + ((lane >> 4) << 3) + (lane & 7);
                uint32_t addr = sX + 32768 + (uint32_t)xr * 256 + ((((xc >> 3) ^ (xr & 7)) & 15) << 4);
                ldsm_x4(bl[pb], addr);
            }
            #pragma unroll
            for (int pb = 0; pb < 4; pb++) {
                mma_f16(C1[2*pb],   aH[ks], bl[pb]);
                mma_f16(C1[2*pb+1], aH[ks], bl[pb] + 2);
            }
            #pragma unroll
            for (int pb = 0; pb < 4; pb++) {
                mma_f16(C1[2*pb],   aL[ks], bh[pb]);
                mma_f16(C1[2*pb+1], aL[ks], bh[pb] + 2);
            }
        }

        // ---- softmax (max-free): exp, row-sum partials, cross-warp reduce ----
        float pr[16];
        #pragma unroll
        for (int b = 0; b < 8; b++) {
            #pragma unroll
            for (int q = 0; q < 4; q++) C1[b][q] = __expf(TEMP * C1[b][q]);
            pr[2*b]   = C1[b][0] + C1[b][2];   // row 2j
            pr[2*b+1] = C1[b][1] + C1[b][3];   // row 2j+1
        }
        #pragma unroll
        for (int vv = 0; vv < 16; vv++) {
            pr[vv] += __shfl_xor_sync(0xffffffffu, pr[vv], 4);
            pr[vv] += __shfl_xor_sync(0xffffffffu, pr[vv], 8);
            pr[vv] += __shfl_xor_sync(0xffffffffu, pr[vv], 16);
        }
        if (lane < 4) {  // g == 0, j = lane
            #pragma unroll
            for (int b = 0; b < 8; b++) {
                sSum[(w & 3) * 128 + R0 + b * 8 + 2 * lane]     = pr[2*b];
                sSum[(w & 3) * 128 + R0 + b * 8 + 2 * lane + 1] = pr[2*b+1];
            }
        }
        __syncthreads();
        if (tid < 128) {
            float tot = sSum[tid] + sSum[128 + tid] + sSum[256 + tid] + sSum[384 + tid];
            invS[tid] = 1.0f / tot;
        }
        __syncthreads();

        // ---- scale + pack R fragments (registers only) ----
        uint32_t rA[4][4];
        #pragma unroll
        for (int b = 0; b < 8; b++) {
            int row = R0 + b * 8 + 2 * j;
            int grow = t * TILE + row;
            float i0 = invS[row], i1 = invS[row + 1];
            if (grow >= N)     i0 = 0.0f;
            if (grow + 1 >= N) i1 = 0.0f;
            float r0 = C1[b][0] * i0, r1 = C1[b][1] * i1;
            float r2 = C1[b][2] * i0, r3 = C1[b][3] * i1;
            cacc0 += r0 + r1;
            cacc1 += r2 + r3;
            rA[b >> 1][(b & 1) * 2 + 0] = pack_f2h2(r0, r1);
            rA[b >> 1][(b & 1) * 2 + 1] = pack_f2h2(r2, r3);
            if (LAST) {
                if (grow < N) {
                    r_out[(size_t)grow * K + kc0 + g]     = r0;
                    r_out[(size_t)grow * K + kc0 + g + 8] = r2;
                }
                if (grow + 1 < N) {
                    r_out[(size_t)(grow + 1) * K + kc0 + g]     = r1;
                    r_out[(size_t)(grow + 1) * K + kc0 + g + 8] = r3;
                }
            }
        }

        // ---- GEMM2: C2[16 kc x 128 d] += Rh^T . (Xh + Xl) (2-term) ----
        #pragma unroll
        for (int kb = 0; kb < 4; kb++) {
            #pragma unroll
            for (int pb = 0; pb < 8; pb++) {
                int brm = R0 + kb * 16 + (((lane >> 3) & 1) << 3) + (lane & 7);
                int d0c = pb * 16 + ((lane >> 4) << 3);
                uint32_t addr = sX + (uint32_t)brm * 256 + ((((d0c >> 3) ^ (brm & 7)) & 15) << 4);
                uint32_t bth[4], btl[4];
                ldsm_x4t(bth, addr);
                ldsm_x4t(btl, addr + 32768);
                mma_f16(C2[2*pb],   rA[kb], bth);
                mma_f16(C2[2*pb+1], rA[kb], bth + 2);
                mma_f16(C2[2*pb],   rA[kb], btl);
                mma_f16(C2[2*pb+1], rA[kb], btl + 2);
            }
        }
        CP_WAIT0();
        __syncthreads();
    }

    // ---- epilogue: counts ----
    cacc0 += __shfl_xor_sync(0xffffffffu, cacc0, 1);
    cacc0 += __shfl_xor_sync(0xffffffffu, cacc0, 2);
    cacc1 += __shfl_xor_sync(0xffffffffu, cacc1, 1);
    cacc1 += __shfl_xor_sync(0xffffffffu, cacc1, 2);
    if (j == 0) {
        scnt[w * 16 + g]     = cacc0;
        scnt[w * 16 + 8 + g] = cacc1;
    }

    // ---- epilogue: pair-reduce C2 across row halves, then atomics ----
    float* sred = (float*)(sm + OFF_X);   // X dead (sync above)
    __syncthreads();
    if (w < 4) {
        float* dst = sred + (w * 2048 + lane * 64);
        #pragma unroll
        for (int f = 0; f < 16; f++)
            #pragma unroll
            for (int q = 0; q < 4; q++) dst[f * 4 + q] = C2[f][q];
    }
    __syncthreads();
    if (w >= 4) {
        const float* src = sred + ((w - 4) * 2048 + lane * 64);
        float* gm = g_mu_raw + (size_t)(it + 1) * (K * D);
        #pragma unroll
        for (int f = 0; f < 16; f++) {
            int d0 = f * 8 + 2 * j;
            atomicAdd(&gm[(kc0 + g) * D + d0],         C2[f][0] + src[f*4+0]);
            atomicAdd(&gm[(kc0 + g) * D + d0 + 1],     C2[f][1] + src[f*4+1]);
            atomicAdd(&gm[(kc0 + g + 8) * D + d0],     C2[f][2] + src[f*4+2]);
            atomicAdd(&gm[(kc0 + g + 8) * D + d0 + 1], C2[f][3] + src[f*4+3]);
        }
    }
    if (tid < K) {
        int strip = tid >> 4, loc = tid & 15;
        float c = scnt[strip * 16 + loc] + scnt[(strip + 4) * 16 + loc];
        atomicAdd(&g_cc[(it + 1) * K + tid], c);
    }
}

// ---------------------------------------------------------------------------
extern "C" void kernel_launch(void* const* d_in, const int* in_sizes, int n_in,
                              void* d_out, int out_size) {
    const float* embeds = (const float*)d_in[0];
    const float* init   = (const float*)d_in[1];
    int N = in_sizes[0] / D;
    int nT = (N + TILE - 1) / TILE;
    if (nT > NT_MAX) nT = NT_MAX;
    float* out_mu = (float*)d_out;
    float* out_r  = (float*)d_out + K * D;

    cudaFuncSetAttribute(iter_kernel<false>, cudaFuncAttributeMaxDynamicSharedMemorySize, SMEM_TOTAL);
    cudaFuncSetAttribute(iter_kernel<true>,  cudaFuncAttributeMaxDynamicSharedMemorySize, SMEM_TOTAL);

    int rowsPad = nT * TILE;
    prep_kernel<<<(rowsPad + 7) / 8, 256>>>(embeds, N, rowsPad);
    zero_kernel<<<(ITERS * K * D + 511) / 512, 512>>>();

    for (int it = 0; it < ITERS; it++) {
        if (it == ITERS - 1)
            iter_kernel<true><<<NB, 256, SMEM_TOTAL>>>(out_r, init, N, nT, it);
        else
            iter_kernel<false><<<NB, 256, SMEM_TOTAL>>>(nullptr, init, N, nT, it);
    }
    final_mu_kernel<<<K, 128>>>(out_mu);
}

// round 15
// speedup vs baseline: 1.1558x; 1.1558x over previous
#include <cuda_runtime.h>
#include <cuda_fp16.h>
#include <cstdint>

#define D 128
#define K 64
#define TILE 128
#define NT_MAX 1563
#define NB 148
#define TEMP 30.0f
#define EPSn 1e-6f
#define ITERS 11

// smem byte offsets
#define OFF_MU 0                 // MuH 16KB | MuL 16KB (fp16)
#define OFF_X  32768             // buf0: Xh 32K | Xl 32K ; buf1 at +65536
#define OFF_R  163840            // Rh 16K (128 rows x 64 kc x 2B)
#define OFF_CNT 180224           // scratch: snorm/scnt
#define SMEM_TOTAL (OFF_CNT + 2048)

__device__ __align__(16) unsigned char g_x[(size_t)NT_MAX * 65536]; // per tile: Xh 32K | Xl 32K, swizzled fp16
__device__ float g_mu_raw[(ITERS + 1) * K * D];
__device__ float g_cc[(ITERS + 1) * K];

__device__ __forceinline__ uint32_t smem_u32(const void* p) {
    uint32_t a;
    asm("{ .reg .u64 t; cvta.to.shared.u64 t, %1; cvt.u32.u64 %0, t; }" : "=r"(a) : "l"(p));
    return a;
}
__device__ __forceinline__ void ldsm_x4(uint32_t* r, uint32_t a) {
    asm volatile("ldmatrix.sync.aligned.m8n8.x4.shared.b16 {%0,%1,%2,%3}, [%4];"
        : "=r"(r[0]), "=r"(r[1]), "=r"(r[2]), "=r"(r[3]) : "r"(a));
}
__device__ __forceinline__ void ldsm_x4t(uint32_t* r, uint32_t a) {
    asm volatile("ldmatrix.sync.aligned.m8n8.x4.trans.shared.b16 {%0,%1,%2,%3}, [%4];"
        : "=r"(r[0]), "=r"(r[1]), "=r"(r[2]), "=r"(r[3]) : "r"(a));
}
__device__ __forceinline__ void mma_f16(float* c, const uint32_t* a, const uint32_t* b) {
    asm volatile("mma.sync.aligned.m16n8k16.row.col.f32.f16.f16.f32 "
        "{%0,%1,%2,%3}, {%4,%5,%6,%7}, {%8,%9}, {%0,%1,%2,%3};"
        : "+f"(c[0]), "+f"(c[1]), "+f"(c[2]), "+f"(c[3])
        : "r"(a[0]), "r"(a[1]), "r"(a[2]), "r"(a[3]), "r"(b[0]), "r"(b[1]));
}
__device__ __forceinline__ void cp16(uint32_t dst, const void* src) {
    asm volatile("cp.async.cg.shared.global [%0], [%1], 16;" :: "r"(dst), "l"(src) : "memory");
}
#define CP_COMMIT() asm volatile("cp.async.commit_group;" ::: "memory")
#define CP_WAIT0()  asm volatile("cp.async.wait_group 0;" ::: "memory")

__device__ __forceinline__ uint32_t pack_h2(__half a, __half b) {
    __half2 v(a, b);
    return *(uint32_t*)&v;
}

// ---------------------------------------------------------------------------
__global__ void prep_kernel(const float* __restrict__ x, int N, int rowsPad) {
    int w = (blockIdx.x * blockDim.x + threadIdx.x) >> 5;
    int lane = threadIdx.x & 31;
    if (w >= rowsPad) return;
    float4 v = make_float4(0.f, 0.f, 0.f, 0.f);
    if (w < N) {
        v = ((const float4*)(x + (size_t)w * D))[lane];
        float ss = v.x*v.x + v.y*v.y + v.z*v.z + v.w*v.w;
        #pragma unroll
        for (int o = 16; o > 0; o >>= 1) ss += __shfl_xor_sync(0xffffffffu, ss, o);
        float inv = 1.0f / (sqrtf(ss) + EPSn);
        v.x *= inv; v.y *= inv; v.z *= inv; v.w *= inv;
    }
    float f[4] = {v.x, v.y, v.z, v.w};
    __half h[4], lo[4];
    #pragma unroll
    for (int i = 0; i < 4; i++) {
        h[i]  = __float2half(f[i]);
        lo[i] = __float2half(f[i] - __half2float(h[i]));
    }
    uint2 uh, ul;
    uh.x = pack_h2(h[0], h[1]);  uh.y = pack_h2(h[2], h[3]);
    ul.x = pack_h2(lo[0], lo[1]); ul.y = pack_h2(lo[2], lo[3]);
    int t = w >> 7, rl = w & 127, d0 = lane * 4;
    uint32_t off = (uint32_t)rl * 256 + ((((d0 >> 3) ^ (rl & 7)) & 15) << 4) + ((d0 & 7) << 1);
    unsigned char* base = g_x + (size_t)t * 65536;
    *(uint2*)(base + off)         = uh;
    *(uint2*)(base + 32768 + off) = ul;
}

// ---------------------------------------------------------------------------
__global__ void zero_kernel() {
    int i = blockIdx.x * 512 + threadIdx.x;
    if (i < ITERS * K * D) g_mu_raw[K * D + i] = 0.0f;
    if (i < (ITERS + 1) * K) g_cc[i] = 0.0f;
}

__global__ void final_mu_kernel(float* __restrict__ mu_out) {
    int k = blockIdx.x, d = threadIdx.x;
    mu_out[k * D + d] = g_mu_raw[ITERS * K * D + k * D + d] / g_cc[ITERS * K + k];
}

// ---------------------------------------------------------------------------
template<bool LAST>
__global__ void __launch_bounds__(256, 1) iter_kernel(float* __restrict__ r_out,
                                                      const float* __restrict__ mu_init,
                                                      int N, int nT, int it) {
    extern __shared__ unsigned char sm[];
    int tid = threadIdx.x, w = tid >> 5, lane = tid & 31;
    int bid = blockIdx.x;
    int t0 = (int)((long long)bid * nT / gridDim.x);
    int t1 = (int)((long long)(bid + 1) * nT / gridDim.x);
    if (t0 >= t1) return;
    uint32_t sb = smem_u32(sm);
    uint32_t sMuH = sb + OFF_MU;
    uint32_t sR   = sb + OFF_R;

    // issue X(t0) load (64KB) first
    {
        const unsigned char* gx = g_x + (size_t)t0 * 65536;
        #pragma unroll
        for (int j = 0; j < 16; j++)
            cp16(sb + OFF_X + (tid + 256 * j) * 16, gx + (tid + 256 * j) * 16);
    }
    CP_COMMIT();

    // ---- fused mu update: v = raw/cnt, normalize, split fp16 hi/lo -> sMu ----
    {
        int kk = tid & 63, dpart = tid >> 6;
        const float* msrc = (it == 0) ? mu_init : (g_mu_raw + (size_t)it * (K * D));
        float cinv = (it == 0) ? 1.0f : (1.0f / g_cc[it * K + kk]);
        const float* row = msrc + kk * D + dpart * 32;
        float v[32];
        float ss = 0.0f;
        #pragma unroll
        for (int j = 0; j < 32; j++) {
            float x = row[j] * cinv;
            v[j] = x;
            ss += x * x;
        }
        float* snorm = (float*)(sm + OFF_CNT);
        snorm[tid] = ss;
        __syncthreads();
        float tot = snorm[kk] + snorm[kk + 64] + snorm[kk + 128] + snorm[kk + 192];
        float inv = 1.0f / (sqrtf(tot) + EPSn);
        #pragma unroll
        for (int j = 0; j < 32; j += 2) {
            float n0 = v[j] * inv, n1 = v[j + 1] * inv;
            __half h0 = __float2half(n0), h1 = __float2half(n1);
            __half l0 = __float2half(n0 - __half2float(h0));
            __half l1 = __float2half(n1 - __half2float(h1));
            int d = dpart * 32 + j;
            uint32_t off = (uint32_t)kk * 256 + ((((d >> 3) ^ (kk & 7)) & 15) << 4) + ((d & 7) << 1);
            *(uint32_t*)(sm + OFF_MU + off)         = pack_h2(h0, h1);
            *(uint32_t*)(sm + OFF_MU + 16384 + off) = pack_h2(l0, l1);
        }
    }
    CP_WAIT0();
    __syncthreads();

    float C2[8][4];
    #pragma unroll
    for (int f = 0; f < 8; f++)
        #pragma unroll
        for (int q = 0; q < 4; q++) C2[f][q] = 0.0f;
    float cacc[16];
    #pragma unroll
    for (int j = 0; j < 16; j++) cacc[j] = 0.0f;

    int m0  = w * 16;                       // GEMM1 row strip
    int kc0 = (w & 3) * 16;                 // GEMM2 cluster strip
    int db  = (w >> 2) * 64;                // GEMM2 d half
    int g = lane >> 2, j2 = lane & 3;

    for (int t = t0; t < t1; t++) {
        int buf = (t - t0) & 1;
        uint32_t sX = sb + OFF_X + buf * 65536;       // Xh; Xl at +32768
        if (t + 1 < t1) {
            const unsigned char* gx = g_x + (size_t)(t + 1) * 65536;
            uint32_t dst = sb + OFF_X + (buf ^ 1) * 65536;
            #pragma unroll
            for (int j = 0; j < 16; j++)
                cp16(dst + (tid + 256 * j) * 16, gx + (tid + 256 * j) * 16);
        }
        CP_COMMIT();

        // ---- GEMM1: C1[16 rows x 64 kc] = X . Mu^T (3-term split) ----
        float C1[8][4];
        #pragma unroll
        for (int f = 0; f < 8; f++)
            #pragma unroll
            for (int q = 0; q < 4; q++) C1[f][q] = 0.0f;
        #pragma unroll
        for (int ks = 0; ks < 8; ks++) {
            uint32_t ah[4], al[4];
            int ar = m0 + (lane & 15);
            int ac = ks * 16 + ((lane >> 4) << 3);
            uint32_t aaddr = sX + (uint32_t)ar * 256 + ((((ac >> 3) ^ (ar & 7)) & 15) << 4);
            ldsm_x4(ah, aaddr);
            ldsm_x4(al, aaddr + 32768);
            #pragma unroll
            for (int fp = 0; fp < 4; fp++) {
                int brow = 16 * fp + ((lane >> 4) << 3) + (lane & 7);
                int bc = ks * 16 + (((lane >> 3) & 1) << 3);
                uint32_t baddr = sMuH + (uint32_t)brow * 256 + ((((bc >> 3) ^ (brow & 7)) & 15) << 4);
                uint32_t bh4[4], bl4[4];
                ldsm_x4(bh4, baddr);
                ldsm_x4(bl4, baddr + 16384);
                mma_f16(C1[2*fp],   ah, bh4);
                mma_f16(C1[2*fp],   al, bh4);
                mma_f16(C1[2*fp],   ah, bl4);
                mma_f16(C1[2*fp+1], ah, bh4 + 2);
                mma_f16(C1[2*fp+1], al, bh4 + 2);
                mma_f16(C1[2*fp+1], ah, bl4 + 2);
            }
        }

        // ---- softmax (max-free; |logit| <= ~30) ----
        int grow0 = t * TILE + m0 + g;
        int grow1 = grow0 + 8;
        float s0 = 0.0f, s1 = 0.0f;
        #pragma unroll
        for (int f = 0; f < 8; f++) {
            #pragma unroll
            for (int q = 0; q < 4; q++) C1[f][q] = __expf(TEMP * C1[f][q]);
            s0 += C1[f][0] + C1[f][1];
            s1 += C1[f][2] + C1[f][3];
        }
        s0 += __shfl_xor_sync(0xffffffffu, s0, 1); s0 += __shfl_xor_sync(0xffffffffu, s0, 2);
        s1 += __shfl_xor_sync(0xffffffffu, s1, 1); s1 += __shfl_xor_sync(0xffffffffu, s1, 2);
        float inv0 = (grow0 < N) ? 1.0f / s0 : 0.0f;
        float inv1 = (grow1 < N) ? 1.0f / s1 : 0.0f;
        int row0 = m0 + g, row1 = row0 + 8;
        #pragma unroll
        for (int f = 0; f < 8; f++) {
            float r0a = C1[f][0] * inv0, r0b = C1[f][1] * inv0;
            float r1a = C1[f][2] * inv1, r1b = C1[f][3] * inv1;
            cacc[2*f]   += r0a + r1a;
            cacc[2*f+1] += r0b + r1b;
            int kc = 8 * f + 2 * j2;
            {
                uint32_t off = (uint32_t)row0 * 128 + (((f ^ (row0 & 7)) & 7) << 4) + (j2 << 2);
                *(uint32_t*)(sm + OFF_R + off) =
                    pack_h2(__float2half(r0a), __float2half(r0b));
            }
            {
                uint32_t off = (uint32_t)row1 * 128 + (((f ^ (row1 & 7)) & 7) << 4) + (j2 << 2);
                *(uint32_t*)(sm + OFF_R + off) =
                    pack_h2(__float2half(r1a), __float2half(r1b));
            }
            if (LAST) {
                if (grow0 < N) *(float2*)(r_out + (size_t)grow0 * K + kc) = make_float2(r0a, r0b);
                if (grow1 < N) *(float2*)(r_out + (size_t)grow1 * K + kc) = make_float2(r1a, r1b);
            }
        }
        __syncthreads();

        // ---- GEMM2: C2[16 kc x 64 d] += Rh^T . Xh (single term) ----
        #pragma unroll
        for (int ks = 0; ks < 8; ks++) {
            int row0k = ks * 16;
            uint32_t ah[4];
            int arm = row0k + (lane & 7) + ((lane >> 4) << 3);
            int acm = kc0 + ((lane >> 3) & 1) * 8;
            uint32_t aaddr = sR + (uint32_t)arm * 128 + ((((acm >> 3) ^ (arm & 7)) & 7) << 4);
            ldsm_x4t(ah, aaddr);
            #pragma unroll
            for (int fp = 0; fp < 4; fp++) {
                int brm = row0k + (((lane >> 3) & 1) << 3) + (lane & 7);
                int d0c = db + 16 * fp + ((lane >> 4) << 3);
                uint32_t baddr = sX + (uint32_t)brm * 256 + ((((d0c >> 3) ^ (brm & 7)) & 15) << 4);
                uint32_t bh4[4];
                ldsm_x4t(bh4, baddr);
                mma_f16(C2[2*fp],   ah, bh4);
                mma_f16(C2[2*fp+1], ah, bh4 + 2);
            }
        }
        CP_WAIT0();
        __syncthreads();
    }

    // ---- epilogue: counts ----
    float* scnt = (float*)(sm + OFF_CNT);
    #pragma unroll
    for (int j = 0; j < 16; j++) {
        cacc[j] += __shfl_xor_sync(0xffffffffu, cacc[j], 4);
        cacc[j] += __shfl_xor_sync(0xffffffffu, cacc[j], 8);
        cacc[j] += __shfl_xor_sync(0xffffffffu, cacc[j], 16);
    }
    if (lane < 4) {
        #pragma unroll
        for (int f = 0; f < 8; f++) {
            scnt[w * 64 + 8 * f + 2 * lane]     = cacc[2*f];
            scnt[w * 64 + 8 * f + 2 * lane + 1] = cacc[2*f+1];
        }
    }
    __syncthreads();
    if (tid < K) {
        float c = 0.0f;
        #pragma unroll
        for (int ww = 0; ww < 8; ww++) c += scnt[ww * 64 + tid];
        atomicAdd(&g_cc[(it + 1) * K + tid], c);
    }
    // ---- epilogue: mean via atomics into next slot ----
    float* gm = g_mu_raw + (size_t)(it + 1) * (K * D);
    #pragma unroll
    for (int f = 0; f < 8; f++) {
        int d0 = db + 8 * f + 2 * j2;
        atomicAdd(&gm[(kc0 + g) * D + d0],         C2[f][0]);
        atomicAdd(&gm[(kc0 + g) * D + d0 + 1],     C2[f][1]);
        atomicAdd(&gm[(kc0 + g + 8) * D + d0],     C2[f][2]);
        atomicAdd(&gm[(kc0 + g + 8) * D + d0 + 1], C2[f][3]);
    }
}

// ---------------------------------------------------------------------------
extern "C" void kernel_launch(void* const* d_in, const int* in_sizes, int n_in,
                              void* d_out, int out_size) {
    const float* embeds = (const float*)d_in[0];
    const float* init   = (const float*)d_in[1];
    int N = in_sizes[0] / D;
    int nT = (N + TILE - 1) / TILE;
    if (nT > NT_MAX) nT = NT_MAX;
    float* out_mu = (float*)d_out;
    float* out_r  = (float*)d_out + K * D;

    cudaFuncSetAttribute(iter_kernel<false>, cudaFuncAttributeMaxDynamicSharedMemorySize, SMEM_TOTAL);
    cudaFuncSetAttribute(iter_kernel<true>,  cudaFuncAttributeMaxDynamicSharedMemorySize, SMEM_TOTAL);

    int rowsPad = nT * TILE;
    prep_kernel<<<(rowsPad + 7) / 8, 256>>>(embeds, N, rowsPad);
    zero_kernel<<<(ITERS * K * D + 511) / 512, 512>>>();

    for (int it = 0; it < ITERS; it++) {
        if (it == ITERS - 1)
            iter_kernel<true><<<NB, 256, SMEM_TOTAL>>>(out_r, init, N, nT, it);
        else
            iter_kernel<false><<<NB, 256, SMEM_TOTAL>>>(nullptr, init, N, nT, it);
    }
    final_mu_kernel<<<K, 128>>>(out_mu);
}